// round 5
// baseline (speedup 1.0000x reference)
#include <cuda_runtime.h>
#include <cuda_bf16.h>

// Problem shape (fixed for this bench problem)
#define SEQ  1024
#define BAT  512
#define NTAG 64
#define TSTRIDE (BAT * NTAG)
#define LN2 0.69314718055994531f

typedef unsigned long long ull;

// Scratch (device globals: allocation-free rule)
__device__ float g_denom[BAT];
__device__ float g_score[BAT];
__device__ int   g_maskT[BAT * SEQ];
__device__ int   g_tags_is64;
__device__ int   g_mask_ones;

// named barrier over the 2 forward warps (threads 0..63)
#define BAR1() asm volatile("bar.sync 1, 64;" ::: "memory")

// ---------------------------------------------------------------------------
__global__ void detect_tags_kernel(const int* __restrict__ tags32) {
    int is64 = 1;
    for (int i = 1; i < 128; i += 2)
        if (tags32[i] != 0) { is64 = 0; break; }
    g_tags_is64 = is64;
    g_mask_ones = 1;
}

__device__ __forceinline__ int load_tag(const void* tags, size_t idx, int is64) {
    if (is64) return (int)((const long long*)tags)[idx];
    return ((const int*)tags)[idx];
}

// ---------------------------------------------------------------------------
__global__ void mask_transpose_kernel(const int* __restrict__ mask) {
    int idx = blockIdx.x * blockDim.x + threadIdx.x;
    if (idx < SEQ * BAT) {
        int t = idx / BAT;
        int b = idx - t * BAT;
        int v = mask[idx];
        g_maskT[b * SEQ + t] = v;
        if (v != 1) g_mask_ones = 0;   // benign race: all writers store 0
    }
}

// ---------------------------------------------------------------------------
// One fused linear-space step for TWO independent chains (fast path).
// Thread j owns column j of both chains. All register indices compile-time.
// Invariant per chain: alpha_j = m0 + e_sum*ln2 + log(s_j).
// ---------------------------------------------------------------------------
__device__ __forceinline__ void fstep2(
    const float* __restrict__ rdA, float* __restrict__ wrA,
    const float* __restrict__ rdB, float* __restrict__ wrB,
    int j, const ull* __restrict__ Ep,
    float rawA, float rawB, int& esA, int& esB)
{
    // per-step multipliers (MUFU, off critical path — hidden under the dots)
    const float cA = __expf(rawA);
    const float cB = __expf(rawB);

    // renorm scale from broadcast s_0 (exact power of 2)
    const float s0A = rdA[0];
    const float s0B = rdB[0];
    int exA = (__float_as_int(s0A) >> 23) & 0xFF;
    int exB = (__float_as_int(s0B) >> 23) & 0xFF;
    exA = max(1, min(exA, 253));
    exB = max(1, min(exB, 253));
    esA += exA - 127;
    esB += exB - 127;
    const float rscA = __int_as_float((254 - exA) << 23);
    const float rscB = __int_as_float((254 - exB) << 23);

    // two interleaved 64-wide dots in packed f32x2, 4 accumulators each
    ull aA0 = 0ull, aA1 = 0ull, aA2 = 0ull, aA3 = 0ull;
    ull aB0 = 0ull, aB1 = 0ull, aB2 = 0ull, aB3 = 0ull;
    const float4* sA4 = (const float4*)rdA;
    const float4* sB4 = (const float4*)rdB;
#pragma unroll
    for (int i = 0; i < 16; i += 2) {
        float4 xA0 = sA4[i];
        float4 xA1 = sA4[i + 1];
        float4 xB0 = sB4[i];
        float4 xB1 = sB4[i + 1];
        ull pA0, pA1, pA2, pA3, pB0, pB1, pB2, pB3;
        asm("mov.b64 %0, {%1, %2};" : "=l"(pA0) : "f"(xA0.x), "f"(xA0.y));
        asm("mov.b64 %0, {%1, %2};" : "=l"(pA1) : "f"(xA0.z), "f"(xA0.w));
        asm("mov.b64 %0, {%1, %2};" : "=l"(pA2) : "f"(xA1.x), "f"(xA1.y));
        asm("mov.b64 %0, {%1, %2};" : "=l"(pA3) : "f"(xA1.z), "f"(xA1.w));
        asm("mov.b64 %0, {%1, %2};" : "=l"(pB0) : "f"(xB0.x), "f"(xB0.y));
        asm("mov.b64 %0, {%1, %2};" : "=l"(pB1) : "f"(xB0.z), "f"(xB0.w));
        asm("mov.b64 %0, {%1, %2};" : "=l"(pB2) : "f"(xB1.x), "f"(xB1.y));
        asm("mov.b64 %0, {%1, %2};" : "=l"(pB3) : "f"(xB1.z), "f"(xB1.w));
        asm("fma.rn.f32x2 %0, %1, %2, %0;" : "+l"(aA0) : "l"(pA0), "l"(Ep[2 * i + 0]));
        asm("fma.rn.f32x2 %0, %1, %2, %0;" : "+l"(aB0) : "l"(pB0), "l"(Ep[2 * i + 0]));
        asm("fma.rn.f32x2 %0, %1, %2, %0;" : "+l"(aA1) : "l"(pA1), "l"(Ep[2 * i + 1]));
        asm("fma.rn.f32x2 %0, %1, %2, %0;" : "+l"(aB1) : "l"(pB1), "l"(Ep[2 * i + 1]));
        asm("fma.rn.f32x2 %0, %1, %2, %0;" : "+l"(aA2) : "l"(pA2), "l"(Ep[2 * i + 2]));
        asm("fma.rn.f32x2 %0, %1, %2, %0;" : "+l"(aB2) : "l"(pB2), "l"(Ep[2 * i + 2]));
        asm("fma.rn.f32x2 %0, %1, %2, %0;" : "+l"(aA3) : "l"(pA3), "l"(Ep[2 * i + 3]));
        asm("fma.rn.f32x2 %0, %1, %2, %0;" : "+l"(aB3) : "l"(pB3), "l"(Ep[2 * i + 3]));
    }
    asm("add.rn.f32x2 %0, %0, %1;" : "+l"(aA0) : "l"(aA2));
    asm("add.rn.f32x2 %0, %0, %1;" : "+l"(aB0) : "l"(aB2));
    asm("add.rn.f32x2 %0, %0, %1;" : "+l"(aA1) : "l"(aA3));
    asm("add.rn.f32x2 %0, %0, %1;" : "+l"(aB1) : "l"(aB3));
    asm("add.rn.f32x2 %0, %0, %1;" : "+l"(aA0) : "l"(aA1));
    asm("add.rn.f32x2 %0, %0, %1;" : "+l"(aB0) : "l"(aB1));
    float lA, hA, lB, hB;
    asm("mov.b64 {%0, %1}, %2;" : "=f"(lA), "=f"(hA) : "l"(aA0));
    asm("mov.b64 {%0, %1}, %2;" : "=f"(lB), "=f"(hB) : "l"(aB0));

    wrA[j] = (lA + hA) * (cA * rscA);
    wrB[j] = (lB + hB) * (cB * rscB);
    BAR1();
}

// ---------------------------------------------------------------------------
// Log-space general-path chain (mask not all ones). Threads 0..63, one batch.
// ---------------------------------------------------------------------------
__device__ void general_chain(
    int b, int j, const ull* __restrict__ Ep,
    const float* __restrict__ logits, const float* __restrict__ startt,
    const float* __restrict__ endt,
    float* __restrict__ se0, float* __restrict__ se1,
    volatile float* __restrict__ aux)
{
    const int* mrow = &g_maskT[b * SEQ];
    const float* lp = logits + (size_t)b * NTAG + j;

    float alpha = startt[j] + lp[0];
    if (j == 0) aux[0] = alpha;
    BAR1();
    float m = aux[0];

    float logit_next = lp[(size_t)1 * TSTRIDE];
    float* bufs[2] = {se0, se1};

    for (int t = 1; t < SEQ; t++) {
        float* buf = bufs[t & 1];
        const float logit = logit_next;
        if (t + 1 < SEQ) logit_next = lp[(size_t)(t + 1) * TSTRIDE];
        const int mk = mrow[t];

        buf[j] = __expf(alpha - m);
        if (j == 0) aux[1] = alpha;
        BAR1();

        ull acc0 = 0ull, acc1 = 0ull;
        const float4* s4 = (const float4*)buf;
#pragma unroll
        for (int i = 0; i < NTAG / 4; i++) {
            float4 sv = s4[i];
            ull p0, p1;
            asm("mov.b64 %0, {%1, %2};" : "=l"(p0) : "f"(sv.x), "f"(sv.y));
            asm("mov.b64 %0, {%1, %2};" : "=l"(p1) : "f"(sv.z), "f"(sv.w));
            asm("fma.rn.f32x2 %0, %1, %2, %0;" : "+l"(acc0) : "l"(p0), "l"(Ep[2 * i]));
            asm("fma.rn.f32x2 %0, %1, %2, %0;" : "+l"(acc1) : "l"(p1), "l"(Ep[2 * i + 1]));
        }
        float q0, q1, q2, q3;
        asm("mov.b64 {%0, %1}, %2;" : "=f"(q0), "=f"(q1) : "l"(acc0));
        asm("mov.b64 {%0, %1}, %2;" : "=f"(q2), "=f"(q3) : "l"(acc1));
        const float v = (q0 + q1) + (q2 + q3);
        const float na = logit + m + __logf(v);
        alpha = mk ? na : alpha;
        BAR1();
        m = aux[1];
    }

    // logsumexp over j of (alpha_j + end_j)
    const int w = j >> 5;
    const int l = j & 31;
    float x = alpha + endt[j];
    float mm = x;
#pragma unroll
    for (int o = 16; o > 0; o >>= 1)
        mm = fmaxf(mm, __shfl_xor_sync(0xffffffffu, mm, o));
    if (l == 0) aux[2 + w] = mm;
    BAR1();
    mm = fmaxf(aux[2], aux[3]);
    float e = __expf(x - mm);
#pragma unroll
    for (int o = 16; o > 0; o >>= 1)
        e += __shfl_xor_sync(0xffffffffu, e, o);
    if (l == 0) aux[4 + w] = e;
    BAR1();
    if (j == 0) g_denom[b] = mm + logf(aux[4] + aux[5]);
    BAR1();
}

// ---------------------------------------------------------------------------
// Fused kernel: warps 0-1 = forward for batches (2k, 2k+1), interleaved.
//               warp 2 = score for batch 2k, warp 3 = score for batch 2k+1.
// ---------------------------------------------------------------------------
__global__ __launch_bounds__(128) void crf_fused2_kernel(
    const float* __restrict__ logits,   // [S, B, T]
    const void*  __restrict__ tags,     // [S, B] int32/int64 (detected)
    const float* __restrict__ trans,    // [T, T]
    const float* __restrict__ startt,   // [T]
    const float* __restrict__ endt)     // [T]
{
    const int b0 = 2 * blockIdx.x;
    const int b1 = b0 + 1;
    const int tid = threadIdx.x;

    // ===================== score warps (threads 64-127) =====================
    if (tid >= 64) {
        const int b = (tid < 96) ? b0 : b1;
        const int lane = tid & 31;
        const int is64 = g_tags_is64;
        const int* mrow = &g_maskT[b * SEQ];
        float s = 0.f;
        int msum = 0;
        for (int t = lane; t < SEQ; t += 32) {
            const int tg = load_tag(tags, (size_t)t * BAT + b, is64);
            const int mt = mrow[t];
            msum += mt;
            if (t < SEQ - 1) {
                const int tgn = load_tag(tags, (size_t)(t + 1) * BAT + b, is64);
                const int mtn = mrow[t + 1];
                s += trans[tg * NTAG + tgn] * (float)mtn;
                s += logits[((size_t)t * BAT + b) * NTAG + tg] * (float)mt;
            }
        }
#pragma unroll
        for (int o = 16; o > 0; o >>= 1) {
            s += __shfl_xor_sync(0xffffffffu, s, o);
            msum += __shfl_xor_sync(0xffffffffu, msum, o);
        }
        if (lane == 0) {
            const int last_idx = msum - 1;
            const int last_tag = load_tag(tags, (size_t)last_idx * BAT + b, is64);
            const int tg0 = load_tag(tags, (size_t)b, is64);
            const float mlast = (float)mrow[SEQ - 1];
            g_score[b] = s + startt[tg0] + endt[last_tag]
                       + logits[((size_t)(SEQ - 1) * BAT + b) * NTAG + last_tag] * mlast;
        }
        return;  // never touches named barrier 1
    }

    // ===================== forward threads (0..63), column j ================
    const int j = tid;
    const int w = j >> 5;
    const int l = j & 31;

    // E column packed: Ep[i] = (exp(trans[2i][j]), exp(trans[2i+1][j]))
    ull Ep[NTAG / 2];
#pragma unroll
    for (int i = 0; i < NTAG / 2; i++) {
        float e0 = __expf(trans[(2 * i) * NTAG + j]);
        float e1 = __expf(trans[(2 * i + 1) * NTAG + j]);
        asm("mov.b64 %0, {%1, %2};" : "=l"(Ep[i]) : "f"(e0), "f"(e1));
    }

    __shared__ float seA[2][NTAG];
    __shared__ float seB[2][NTAG];
    __shared__ float aux[8];

    if (!g_mask_ones) {
        // -------- GENERAL PATH: two sequential log-space chains --------
        general_chain(b0, j, Ep, logits, startt, endt, seA[0], seA[1], aux);
        general_chain(b1, j, Ep, logits, startt, endt, seA[0], seA[1], aux);
        return;
    }

    // -------- FAST PATH: two interleaved linear-space chains --------
    const float a0A = startt[j] + logits[(size_t)b0 * NTAG + j];
    const float a0B = startt[j] + logits[(size_t)b1 * NTAG + j];
    if (j == 0) { aux[0] = a0A; aux[1] = a0B; }
    BAR1();
    const float m0A = aux[0];
    const float m0B = aux[1];
    seA[0][j] = __expf(a0A - m0A);
    seB[0][j] = __expf(a0B - m0B);

    const float* lpA = logits + (size_t)b0 * NTAG + j;
    const float* lpB = logits + (size_t)b1 * NTAG + j;

    // prefetch rings, depth 8 each
    float rawA[8], rawB[8];
#pragma unroll
    for (int u = 0; u < 8; u++) {
        rawA[u] = lpA[(size_t)(1 + u) * TSTRIDE];
        rawB[u] = lpB[(size_t)(1 + u) * TSTRIDE];
    }
    BAR1();  // se*[0] visible

    int esA = 0, esB = 0;
    for (int t0 = 1; t0 + 7 <= SEQ - 1; t0 += 8) {
#pragma unroll
        for (int u = 0; u < 8; u++) {
            fstep2(seA[u & 1], seA[(u & 1) ^ 1],
                   seB[u & 1], seB[(u & 1) ^ 1],
                   j, Ep, rawA[u], rawB[u], esA, esB);
            if (t0 + u + 8 <= SEQ - 1) {
                rawA[u] = lpA[(size_t)(t0 + u + 8) * TSTRIDE];
                rawB[u] = lpB[(size_t)(t0 + u + 8) * TSTRIDE];
            }
        }
    }
    // remainder: t = 1017..1023 (7 steps); final s lands in se*[1]
#pragma unroll
    for (int u = 0; u < 7; u++)
        fstep2(seA[u & 1], seA[(u & 1) ^ 1],
               seB[u & 1], seB[(u & 1) ^ 1],
               j, Ep, rawA[u], rawB[u], esA, esB);

    // final logsumexp per chain: x_j = m0 + e_sum*ln2 + log(s_j) + end_j
    const float ej = endt[j];
    float xA = m0A + (float)esA * LN2 + logf(seA[1][j]) + ej;
    float xB = m0B + (float)esB * LN2 + logf(seB[1][j]) + ej;

    float mA = xA, mB = xB;
#pragma unroll
    for (int o = 16; o > 0; o >>= 1) {
        mA = fmaxf(mA, __shfl_xor_sync(0xffffffffu, mA, o));
        mB = fmaxf(mB, __shfl_xor_sync(0xffffffffu, mB, o));
    }
    if (l == 0) { aux[2 + w] = mA; aux[4 + w] = mB; }
    BAR1();
    mA = fmaxf(aux[2], aux[3]);
    mB = fmaxf(aux[4], aux[5]);
    float eA = __expf(xA - mA);
    float eB = __expf(xB - mB);
#pragma unroll
    for (int o = 16; o > 0; o >>= 1) {
        eA += __shfl_xor_sync(0xffffffffu, eA, o);
        eB += __shfl_xor_sync(0xffffffffu, eB, o);
    }
    if (l == 0) { aux[2 + w] = eA; aux[4 + w] = eB; }
    BAR1();
    if (j == 0) {
        g_denom[b0] = mA + logf(aux[2] + aux[3]);
        g_denom[b1] = mB + logf(aux[4] + aux[5]);
    }
}

// ---------------------------------------------------------------------------
// Deterministic final reduction: out = sum_b (score_b - denom_b)
// ---------------------------------------------------------------------------
__global__ void crf_reduce_kernel(float* __restrict__ out) {
    __shared__ float sm[BAT];
    const int i = threadIdx.x;
    sm[i] = g_score[i] - g_denom[i];
    __syncthreads();
    for (int o = BAT / 2; o > 0; o >>= 1) {
        if (i < o) sm[i] += sm[i + o];
        __syncthreads();
    }
    if (i == 0) out[0] = sm[0];
}

// ---------------------------------------------------------------------------
extern "C" void kernel_launch(void* const* d_in, const int* in_sizes, int n_in,
                              void* d_out, int out_size) {
    const float* logits = (const float*)d_in[0];   // [S,B,T] f32
    const void*  tags   = d_in[1];                 // [S,B] i32 or i64
    const int*   mask   = (const int*)d_in[2];     // [S,B] i32
    const float* trans  = (const float*)d_in[3];   // [T,T]
    const float* startt = (const float*)d_in[4];   // [T]
    const float* endt   = (const float*)d_in[5];   // [T]
    float* out = (float*)d_out;

    detect_tags_kernel<<<1, 1>>>((const int*)tags);
    mask_transpose_kernel<<<(SEQ * BAT + 255) / 256, 256>>>(mask);
    crf_fused2_kernel<<<BAT / 2, 128>>>(logits, tags, trans, startt, endt);
    crf_reduce_kernel<<<1, BAT>>>(out);
}

// round 6
// speedup vs baseline: 2.0638x; 2.0638x over previous
#include <cuda_runtime.h>
#include <cuda_bf16.h>

// Problem shape (fixed for this bench problem)
#define SEQ  1024
#define BAT  512
#define NTAG 64
#define TSTRIDE (BAT * NTAG)
#define LN2 0.69314718055994531f

typedef unsigned long long ull;

// Scratch (device globals: allocation-free rule)
__device__ float g_denom[BAT];
__device__ float g_score[BAT];
__device__ int   g_maskT[BAT * SEQ];
__device__ int   g_tags_is64;
__device__ int   g_mask_ones;

// named barrier over the 2 forward warps (threads 0..63); score warp excluded
#define BAR1() asm volatile("bar.sync 1, 64;" ::: "memory")

// ---------------------------------------------------------------------------
__global__ void detect_tags_kernel(const int* __restrict__ tags32) {
    int is64 = 1;
    for (int i = 1; i < 128; i += 2)
        if (tags32[i] != 0) { is64 = 0; break; }
    g_tags_is64 = is64;
    g_mask_ones = 1;
}

__device__ __forceinline__ int load_tag(const void* tags, size_t idx, int is64) {
    if (is64) return (int)((const long long*)tags)[idx];
    return ((const int*)tags)[idx];
}

// ---------------------------------------------------------------------------
__global__ void mask_transpose_kernel(const int* __restrict__ mask) {
    int idx = blockIdx.x * blockDim.x + threadIdx.x;
    if (idx < SEQ * BAT) {
        int t = idx / BAT;
        int b = idx - t * BAT;
        int v = mask[idx];
        g_maskT[b * SEQ + t] = v;
        if (v != 1) g_mask_ones = 0;   // benign race: all writers store 0
    }
}

// ---------------------------------------------------------------------------
// One linear-space forward step (fast path). Thread j owns column j.
// Invariant: alpha_j = m0 + e_sum*ln2 + log(s_j), s in shared (prev buffer).
// se loaded as ulonglong2 -> register pairs feed fma.rn.f32x2 directly (no packs).
// ---------------------------------------------------------------------------
__device__ __forceinline__ float fast_step(
    const float* __restrict__ se_read, float* __restrict__ se_write, int j,
    const ull* __restrict__ Ep, float rawv, int& e_sum)
{
    const float c = __expf(rawv);   // MUFU, hidden under the dot below

    // renorm scale from broadcast s_0 (exact power of 2) — off critical path
    const float s0 = se_read[0];
    int ex = (__float_as_int(s0) >> 23) & 0xFF;
    ex = max(1, min(ex, 253));
    e_sum += ex - 127;
    const float rsc = __int_as_float((254 - ex) << 23);  // 2^(254-ex-127)
    const float cmul = c * rsc;

    // 64-wide dot in packed f32x2: 16 LDS.128 + 32 FFMA2, 4 accumulators
    const ulonglong2* s2 = (const ulonglong2*)se_read;
    ull a0 = 0ull, a1 = 0ull, a2 = 0ull, a3 = 0ull;
#pragma unroll
    for (int i = 0; i < 16; i += 2) {
        ulonglong2 qA = s2[i];
        ulonglong2 qB = s2[i + 1];
        asm("fma.rn.f32x2 %0, %1, %2, %0;" : "+l"(a0) : "l"(qA.x), "l"(Ep[2 * i + 0]));
        asm("fma.rn.f32x2 %0, %1, %2, %0;" : "+l"(a1) : "l"(qA.y), "l"(Ep[2 * i + 1]));
        asm("fma.rn.f32x2 %0, %1, %2, %0;" : "+l"(a2) : "l"(qB.x), "l"(Ep[2 * i + 2]));
        asm("fma.rn.f32x2 %0, %1, %2, %0;" : "+l"(a3) : "l"(qB.y), "l"(Ep[2 * i + 3]));
    }
    asm("add.rn.f32x2 %0, %0, %1;" : "+l"(a0) : "l"(a2));
    asm("add.rn.f32x2 %0, %0, %1;" : "+l"(a1) : "l"(a3));
    asm("add.rn.f32x2 %0, %0, %1;" : "+l"(a0) : "l"(a1));
    float lo, hi;
    asm("mov.b64 {%0, %1}, %2;" : "=f"(lo), "=f"(hi) : "l"(a0));

    const float snew = (lo + hi) * cmul;
    se_write[j] = snew;
    BAR1();
    return snew;
}

// ---------------------------------------------------------------------------
// Fused kernel: threads 0-63 = forward chain, threads 64-95 = gold-path score.
// One block per batch element.
// ---------------------------------------------------------------------------
__global__ __launch_bounds__(96) void crf_fused_kernel(
    const float* __restrict__ logits,   // [S, B, T]
    const void*  __restrict__ tags,     // [S, B] int32/int64 (detected)
    const float* __restrict__ trans,    // [T, T]
    const float* __restrict__ startt,   // [T]
    const float* __restrict__ endt)     // [T]
{
    const int b = blockIdx.x;
    const int tid = threadIdx.x;

    // ===================== score warp (threads 64-95) =====================
    if (tid >= 64) {
        const int lane = tid - 64;
        const int is64 = g_tags_is64;
        const int* mrow = &g_maskT[b * SEQ];
        float s = 0.f;
        int msum = 0;
        for (int t = lane; t < SEQ; t += 32) {
            const int tg = load_tag(tags, (size_t)t * BAT + b, is64);
            const int mt = mrow[t];
            msum += mt;
            if (t < SEQ - 1) {
                const int tgn = load_tag(tags, (size_t)(t + 1) * BAT + b, is64);
                const int mtn = mrow[t + 1];
                s += trans[tg * NTAG + tgn] * (float)mtn;
                s += logits[((size_t)t * BAT + b) * NTAG + tg] * (float)mt;
            }
        }
#pragma unroll
        for (int o = 16; o > 0; o >>= 1) {
            s += __shfl_xor_sync(0xffffffffu, s, o);
            msum += __shfl_xor_sync(0xffffffffu, msum, o);
        }
        if (lane == 0) {
            const int last_idx = msum - 1;
            const int last_tag = load_tag(tags, (size_t)last_idx * BAT + b, is64);
            const int tg0 = load_tag(tags, (size_t)b, is64);
            const float mlast = (float)mrow[SEQ - 1];
            g_score[b] = s + startt[tg0] + endt[last_tag]
                       + logits[((size_t)(SEQ - 1) * BAT + b) * NTAG + last_tag] * mlast;
        }
        return;  // never touches named barrier 1
    }

    // ===================== forward threads (0..63), column j ================
    const int j = tid;
    const int w = j >> 5;
    const int l = j & 31;

    // E column, packed pairs: Ep[i] = (exp(trans[2i][j]), exp(trans[2i+1][j]))
    ull Ep[NTAG / 2];
#pragma unroll
    for (int i = 0; i < NTAG / 2; i++) {
        float e0 = __expf(trans[(2 * i) * NTAG + j]);
        float e1 = __expf(trans[(2 * i + 1) * NTAG + j]);
        asm("mov.b64 %0, {%1, %2};" : "=l"(Ep[i]) : "f"(e0), "f"(e1));
    }

    __shared__ __align__(16) float se[2][NTAG];
    __shared__ float sh_aux[4];

    const float alpha0 = startt[j] + logits[(size_t)b * NTAG + j];
    if (j == 0) sh_aux[0] = alpha0;
    BAR1();
    const float m0 = sh_aux[0];

    const float* lptr = logits + (size_t)b * NTAG + j;

    if (g_mask_ones) {
        // ============== FAST PATH: pure linear-space recurrence ==============
        float sj = __expf(alpha0 - m0);
        se[0][j] = sj;

        // prefetch ring, depth 8
        float raw[8];
#pragma unroll
        for (int u = 0; u < 8; u++)
            raw[u] = lptr[(size_t)(1 + u) * TSTRIDE];
        BAR1();   // se[0] visible

        int e_sum = 0;
        for (int t0 = 1; t0 + 7 <= SEQ - 1; t0 += 8) {
#pragma unroll
            for (int u = 0; u < 8; u++) {
                sj = fast_step(se[u & 1], se[(u & 1) ^ 1], j, Ep, raw[u], e_sum);
                if (t0 + u + 8 <= SEQ - 1)
                    raw[u] = lptr[(size_t)(t0 + u + 8) * TSTRIDE];
            }
        }
        // remainder steps (SEQ-1 = 1023 = 127*8 + 7): t = 1017..1023
#pragma unroll
        for (int u = 0; u < 7; u++)
            sj = fast_step(se[u & 1], se[(u & 1) ^ 1], j, Ep, raw[u], e_sum);

        // final logsumexp over j of (alpha_j + end_j)
        float x = m0 + (float)e_sum * LN2 + logf(sj) + endt[j];
        float mm = x;
#pragma unroll
        for (int o = 16; o > 0; o >>= 1)
            mm = fmaxf(mm, __shfl_xor_sync(0xffffffffu, mm, o));
        if (l == 0) sh_aux[w] = mm;
        BAR1();
        mm = fmaxf(sh_aux[0], sh_aux[1]);
        float e = __expf(x - mm);
#pragma unroll
        for (int o = 16; o > 0; o >>= 1)
            e += __shfl_xor_sync(0xffffffffu, e, o);
        if (l == 0) sh_aux[2 + w] = e;
        BAR1();
        if (j == 0) g_denom[b] = mm + logf(sh_aux[2] + sh_aux[3]);
        return;
    }

    // ============== GENERAL PATH (mask not all ones): log-space ==============
    {
        __shared__ float sm0[2];
        float alpha = alpha0;
        float m = m0;
        const int* mrow = &g_maskT[b * SEQ];
        float logit_next = lptr[(size_t)1 * TSTRIDE];

        for (int t = 1; t < SEQ; t++) {
            const int buf = t & 1;
            const float logit = logit_next;
            if (t + 1 < SEQ) logit_next = lptr[(size_t)(t + 1) * TSTRIDE];
            const int mk = mrow[t];

            se[buf][j] = __expf(alpha - m);
            if (j == 0) sm0[buf] = alpha;
            BAR1();

            ull acc0 = 0ull, acc1 = 0ull;
            const ulonglong2* s2 = (const ulonglong2*)(&se[buf][0]);
#pragma unroll
            for (int i = 0; i < 16; i++) {
                ulonglong2 q = s2[i];
                asm("fma.rn.f32x2 %0, %1, %2, %0;" : "+l"(acc0) : "l"(q.x), "l"(Ep[2 * i]));
                asm("fma.rn.f32x2 %0, %1, %2, %0;" : "+l"(acc1) : "l"(q.y), "l"(Ep[2 * i + 1]));
            }
            asm("add.rn.f32x2 %0, %0, %1;" : "+l"(acc0) : "l"(acc1));
            float q0, q1;
            asm("mov.b64 {%0, %1}, %2;" : "=f"(q0), "=f"(q1) : "l"(acc0));
            const float v = q0 + q1;

            const float na = logit + m + __logf(v);
            alpha = mk ? na : alpha;
            m = sm0[buf];
            BAR1();
        }

        float x = alpha + endt[j];
        float mm = x;
#pragma unroll
        for (int o = 16; o > 0; o >>= 1)
            mm = fmaxf(mm, __shfl_xor_sync(0xffffffffu, mm, o));
        if (l == 0) sh_aux[w] = mm;
        BAR1();
        mm = fmaxf(sh_aux[0], sh_aux[1]);
        float e = __expf(x - mm);
#pragma unroll
        for (int o = 16; o > 0; o >>= 1)
            e += __shfl_xor_sync(0xffffffffu, e, o);
        if (l == 0) sh_aux[2 + w] = e;
        BAR1();
        if (j == 0) g_denom[b] = mm + logf(sh_aux[2] + sh_aux[3]);
    }
}

// ---------------------------------------------------------------------------
// Deterministic final reduction: out = sum_b (score_b - denom_b)
// ---------------------------------------------------------------------------
__global__ void crf_reduce_kernel(float* __restrict__ out) {
    __shared__ float sm[BAT];
    const int i = threadIdx.x;
    sm[i] = g_score[i] - g_denom[i];
    __syncthreads();
    for (int o = BAT / 2; o > 0; o >>= 1) {
        if (i < o) sm[i] += sm[i + o];
        __syncthreads();
    }
    if (i == 0) out[0] = sm[0];
}

// ---------------------------------------------------------------------------
extern "C" void kernel_launch(void* const* d_in, const int* in_sizes, int n_in,
                              void* d_out, int out_size) {
    const float* logits = (const float*)d_in[0];   // [S,B,T] f32
    const void*  tags   = d_in[1];                 // [S,B] i32 or i64
    const int*   mask   = (const int*)d_in[2];     // [S,B] i32
    const float* trans  = (const float*)d_in[3];   // [T,T]
    const float* startt = (const float*)d_in[4];   // [T]
    const float* endt   = (const float*)d_in[5];   // [T]
    float* out = (float*)d_out;

    detect_tags_kernel<<<1, 1>>>((const int*)tags);
    mask_transpose_kernel<<<(SEQ * BAT + 255) / 256, 256>>>(mask);
    crf_fused_kernel<<<BAT, 96>>>(logits, tags, trans, startt, endt);
    crf_reduce_kernel<<<1, BAT>>>(out);
}